// round 12
// baseline (speedup 1.0000x reference)
#include <cuda_runtime.h>
#include <math.h>

#define T_TOK 8192
#define NH 16
#define HD 128
#define CH 64
#define NC 128
#define ROW (NH*HD)   // 2048

// ------------------- device scratch (allocation-free) -------------------
__device__ float gq [T_TOK*ROW];   // q~   (phase12 out)
__device__ float gk [T_TOK*ROW];   // Kbar
__device__ float gv [T_TOK*ROW];   // Vb
__device__ float gg [T_TOK*ROW];   // Kb
__device__ float gM [NC*NH*CH*CH];
__device__ float gCp[NC*NH*HD];

// =========================================================================
// Phase 1+2 fused: conv+SiLU+l2norm+gates straight into smem, then
// cumsum / transform / pair matrices / blocked forward substitution.
// grid (NC, NH), block 512, dyn smem ~149 KB
// =========================================================================
#define P2S 132   // padded row stride (float4-aligned)

__global__ void __launch_bounds__(512) k_phase12(
    const float* __restrict__ qkv, const float* __restrict__ fg,
    const float* __restrict__ beta, const float* __restrict__ cw,
    const float* __restrict__ dtb, const float* __restrict__ alog)
{
    extern __shared__ float sm[];
    float* gcS = sm;               // 64*132 (gates -> cumsum -> ZB = Kb)
    float* qS  = gcS + CH*P2S;     // 64*132 (q -> ZA = Vb)
    float* kS  = qS  + CH*P2S;     // 64*132
    float* vS  = kS  + CH*P2S;     // 64*132
    float* Ls  = vS  + CH*P2S;     // 64*65
    float* bS  = Ls  + CH*65;      // 64

    int c = blockIdx.x, h = blockIdx.y, tid = threadIdx.x;
    int w = tid >> 5, l = tid & 31;
    size_t tbase = ((size_t)c*CH*NH + h)*HD;

    // ================= step A: conv(K=4)+SiLU+l2norm+gates ================
    {
        int tloc0 = w * 4;                    // 4 tokens per warp
        int t0 = c * CH + tloc0;
        int d0 = l * 4;
        int cq = h*HD + d0, ck = ROW + cq, cv = 2*ROW + cq;

        float wq[4][4], wk[4][4], wv[4][4];
#pragma unroll
        for (int e = 0; e < 4; ++e)
#pragma unroll
            for (int j = 0; j < 4; ++j) {
                wq[e][j] = cw[(cq+e)*4 + j];
                wk[e][j] = cw[(ck+e)*4 + j];
                wv[e][j] = cw[(cv+e)*4 + j];
            }
        float ea = expf(alog[h]);
        float dtv[4];
        *(float4*)dtv = *(const float4*)(dtb + h*HD + d0);

        float pq[3][4], pk[3][4], pv[3][4];
#pragma unroll
        for (int j = 0; j < 3; ++j) {
            int ts = t0 - 3 + j;
            if (ts >= 0) {
                const float* row = qkv + (size_t)ts * (3*ROW);
                *(float4*)pq[j] = *(const float4*)(row + cq);
                *(float4*)pk[j] = *(const float4*)(row + ck);
                *(float4*)pv[j] = *(const float4*)(row + cv);
            } else {
#pragma unroll
                for (int e = 0; e < 4; ++e) { pq[j][e]=0.f; pk[j][e]=0.f; pv[j][e]=0.f; }
            }
        }

#pragma unroll
        for (int tt = 0; tt < 4; ++tt) {
            int t = t0 + tt, tloc = tloc0 + tt;
            const float* row = qkv + (size_t)t * (3*ROW);
            float rq[4], rk[4], rv[4], fgv[4];
            *(float4*)rq = *(const float4*)(row + cq);
            *(float4*)rk = *(const float4*)(row + ck);
            *(float4*)rv = *(const float4*)(row + cv);
            *(float4*)fgv = *(const float4*)(fg + (size_t)t*ROW + h*HD + d0);

            float xq[4], xk[4], xv[4];
#pragma unroll
            for (int e = 0; e < 4; ++e) {
                float aq = pq[0][e]*wq[e][0] + pq[1][e]*wq[e][1] + pq[2][e]*wq[e][2] + rq[e]*wq[e][3];
                float ak = pk[0][e]*wk[e][0] + pk[1][e]*wk[e][1] + pk[2][e]*wk[e][2] + rk[e]*wk[e][3];
                float av = pv[0][e]*wv[e][0] + pv[1][e]*wv[e][1] + pv[2][e]*wv[e][2] + rv[e]*wv[e][3];
                xq[e] = aq / (1.f + __expf(-aq));
                xk[e] = ak / (1.f + __expf(-ak));
                xv[e] = av / (1.f + __expf(-av));
            }
#pragma unroll
            for (int j = 0; j < 2; ++j)
#pragma unroll
                for (int e = 0; e < 4; ++e) { pq[j][e]=pq[j+1][e]; pk[j][e]=pk[j+1][e]; pv[j][e]=pv[j+1][e]; }
#pragma unroll
            for (int e = 0; e < 4; ++e) { pq[2][e]=rq[e]; pk[2][e]=rk[e]; pv[2][e]=rv[e]; }

            float sq = xq[0]*xq[0]+xq[1]*xq[1]+xq[2]*xq[2]+xq[3]*xq[3];
            float sk = xk[0]*xk[0]+xk[1]*xk[1]+xk[2]*xk[2]+xk[3]*xk[3];
#pragma unroll
            for (int m = 16; m; m >>= 1) {
                sq += __shfl_xor_sync(~0u, sq, m);
                sk += __shfl_xor_sync(~0u, sk, m);
            }
            float rnq = rsqrtf(sq + 1e-6f) * 0.08838834764831845f; // * D^-1/2
            float rnk = rsqrtf(sk + 1e-6f);

            float oq[4], ok[4], og[4];
#pragma unroll
            for (int e = 0; e < 4; ++e) {
                oq[e] = xq[e] * rnq;
                ok[e] = xk[e] * rnk;
                float gr = fgv[e] + dtv[e];
                float sp = (gr > 20.f) ? gr : log1pf(__expf(gr));
                og[e] = -ea * sp;
            }
            *(float4*)(qS  + tloc*P2S + d0) = *(float4*)oq;
            *(float4*)(kS  + tloc*P2S + d0) = *(float4*)ok;
            *(float4*)(vS  + tloc*P2S + d0) = *(float4*)xv;
            *(float4*)(gcS + tloc*P2S + d0) = *(float4*)og;
            if (l == 0) {
                float bb = beta[t*NH + h];
                bS[tloc] = 1.f / (1.f + __expf(-bb));
            }
        }
    }
    __syncthreads();

    // ---- gc cumsum over t ----
    if (tid < HD) {
        float run = 0.f;
        for (int t = 0; t < CH; ++t) { run += gcS[t*P2S+tid]; gcS[t*P2S+tid] = run; }
    }
    __syncthreads();

    // ---- q~ = q*exp(gc), Kbar = k*exp(gc63-gc), cp = exp(gc63) ----
    for (int i = tid; i < CH*HD; i += 512) {
        int t = i >> 7, k = i & 127;
        float gct = gcS[t*P2S+k];
        float g63 = gcS[63*P2S+k];
        size_t go = tbase + (size_t)t*ROW + k;
        gq[go] = qS[t*P2S+k] * __expf(gct);
        gk[go] = kS[t*P2S+k] * __expf(g63 - gct);
    }
    if (tid < HD) gCp[(c*NH+h)*HD + tid] = __expf(gcS[63*P2S+tid]);

    // ---- pair tiles: warp processes an 8t x 4s tile, lane=(tr,sc) ----
    size_t mbase = (size_t)(c*NH + h) * CH * CH;
    {
        int l5 = tid & 31, tr = l5 >> 2, sc = l5 & 3;
        for (int tile = w; tile < 72; tile += 16) {
            int i = 0;
            while ((i+1)*(i+2) <= tile) ++i;    // tiles before row i = i*(i+1)
            int j = tile - i*(i+1);
            int t = i*8 + tr, s = j*4 + sc;
            const float* gtr = gcS + t*P2S; const float* gsr = gcS + s*P2S;
            const float* ktr = kS  + t*P2S; const float* ksr = kS  + s*P2S;
            const float* qtr = qS  + t*P2S;
            float a = 0.f, m = 0.f;
#pragma unroll 4
            for (int k = 0; k < HD; k += 4) {
                float4 g1 = *(const float4*)(gtr + k);
                float4 g0 = *(const float4*)(gsr + k);
                float4 kt4 = *(const float4*)(ktr + k);
                float4 ks4 = *(const float4*)(ksr + k);
                float4 qt4 = *(const float4*)(qtr + k);
                float e, kv;
                e = __expf(g1.x - g0.x); kv = ks4.x * e; a += kt4.x*kv; m += qt4.x*kv;
                e = __expf(g1.y - g0.y); kv = ks4.y * e; a += kt4.y*kv; m += qt4.y*kv;
                e = __expf(g1.z - g0.z); kv = ks4.z * e; a += kt4.z*kv; m += qt4.z*kv;
                e = __expf(g1.w - g0.w); kv = ks4.w * e; a += kt4.w*kv; m += qt4.w*kv;
            }
            if (s <= t) gM[mbase + t*64 + s] = m;
            if (s <  t) Ls[t*65 + s] = bS[t] * a;
        }
    }
    // zero upper triangle of M (phase3 relies on M[t][s>t] == 0)
    for (int i = tid; i < 4096; i += 512) {
        int t = i >> 6, s = i & 63;
        if (s > t) gM[mbase + i] = 0.f;
    }
    __syncthreads();

    // ---- RHS in place: ZA(qS) = b*v, ZB(gcS) = b*k*exp(gc) ----
    for (int i = tid; i < CH*HD; i += 512) {
        int t = i >> 7, k = i & 127;
        float bb = bS[t];
        float zb = bb * kS[t*P2S+k] * __expf(gcS[t*P2S+k]);
        qS [t*P2S+k] = bb * vS[t*P2S+k];
        gcS[t*P2S+k] = zb;
    }
    __syncthreads();

    // ---- blocked forward substitution (I+L) Z = RHS ----
#pragma unroll
    for (int ib = 0; ib < 4; ++ib) {
        int i0 = ib * 16;
        if (tid < 256) {
            float* Z = (tid < 128) ? (qS + tid) : (gcS + (tid - 128));
            for (int t = i0+1; t < i0+16; ++t) {
                float acc = 0.f;
                const float* lrow = Ls + t*65;
                for (int s = i0; s < t; ++s) acc += lrow[s] * Z[s*P2S];
                Z[t*P2S] -= acc;
            }
        }
        __syncthreads();
        int rows = 48 - 16*ib;
        if (rows > 0) {
            int slots = rows * 128;
            for (int sl = tid; sl < slots; sl += 512) {
                int t  = i0 + 16 + (sl >> 7);
                int c2 = sl & 127;
                float* Z = (c2 < 64) ? (qS + c2*2) : (gcS + (c2-64)*2);
                float2 acc = make_float2(0.f, 0.f);
                const float* lrow = Ls + t*65 + i0;
#pragma unroll
                for (int s = 0; s < 16; ++s) {
                    float lv = lrow[s];
                    float2 zv = *(const float2*)(Z + (i0+s)*P2S);
                    acc.x += lv*zv.x; acc.y += lv*zv.y;
                }
                float2 zt = *(float2*)(Z + t*P2S);
                zt.x -= acc.x; zt.y -= acc.y;
                *(float2*)(Z + t*P2S) = zt;
            }
        }
        __syncthreads();
    }

    // ---- write out: Vb -> gv, Kb -> gg ----
    for (int i = tid; i < CH*HD; i += 512) {
        int t = i >> 7, k = i & 127;
        size_t go = tbase + (size_t)t*ROW + k;
        gv[go] = qS [t*P2S+k];
        gg[go] = gcS[t*P2S+k];
    }
}

// =========================================================================
// Phase 3: sequential chunk scan, float4-per-thread outputs, split-K
// partials, O-pass || S-update on disjoint warp halves, register-prefetched
// staging. grid (8, NH), block 512.
// =========================================================================
#define ST3 132          // k-row stride (float4-aligned)
#define MT3 68           // M row stride

__global__ void __launch_bounds__(512) k_phase3(float* __restrict__ out)
{
    extern __shared__ float sm[];
    float* KbS = sm;                 // 64*132
    float* QtS = KbS + CH*ST3;
    float* KrS = QtS + CH*ST3;
    float* MS  = KrS + CH*ST3;       // 64*68
    float* VbS = MS  + CH*MT3;       // 1024
    float* DS1 = VbS + 1024;         // 1024 (partial / combined D)
    float* DS2 = DS1 + 1024;         // 1024
    float* XS1 = DS2 + 1024;         // 1024 (partial / combined X)
    float* XS2 = XS1 + 1024;         // 1024
    float* cpS = XS2 + 1024;         // 128
    float* S   = cpS + HD;           // 128*16

    int h = blockIdx.y, j0 = blockIdx.x * 16, tid = threadIdx.x;
    int g  = tid >> 8;               // k-half for fused pass
    int id = tid & 255;
    int t  = id >> 2, jq = id & 3;   // (t, j-quad) mapping
    int k0 = g * 64;

    float4 rKb[4], rQt[4], rKr[4], rM[2], rVb;
    float rCp = 0.f;
    int stt[4], sk4[4];
#pragma unroll
    for (int i = 0; i < 4; ++i) {
        int idx = tid + i*512;
        stt[i] = idx >> 5; sk4[i] = (idx & 31) * 4;
    }
    int mtt[2], ms4[2];
#pragma unroll
    for (int i = 0; i < 2; ++i) {
        int f = tid + i*512;
        mtt[i] = f >> 4; ms4[i] = (f & 15) * 4;
    }
    int vtt = tid >> 2, vj4 = (tid & 3) * 4;

    for (int i = tid; i < HD*16; i += 512) S[i] = 0.f;

    // ---- prologue: load + commit chunk 0 ----
    {
        size_t tbase = ((size_t)h)*HD;
#pragma unroll
        for (int i = 0; i < 4; ++i) {
            size_t go = tbase + (size_t)stt[i]*ROW + sk4[i];
            *(float4*)(KbS + stt[i]*ST3 + sk4[i]) = *(const float4*)(gg + go);
            *(float4*)(QtS + stt[i]*ST3 + sk4[i]) = *(const float4*)(gq + go);
            *(float4*)(KrS + stt[i]*ST3 + sk4[i]) = *(const float4*)(gk + go);
        }
#pragma unroll
        for (int i = 0; i < 2; ++i)
            *(float4*)(MS + mtt[i]*MT3 + ms4[i]) =
                *(const float4*)(gM + (size_t)h*CH*CH + mtt[i]*64 + ms4[i]);
        if (tid < 256)
            *(float4*)(VbS + vtt*16 + vj4) =
                *(const float4*)(gv + tbase + (size_t)vtt*ROW + j0 + vj4);
        if (tid < HD) cpS[tid] = gCp[h*HD + tid];
    }
    __syncthreads();

    for (int c = 0; c < NC; ++c) {
        // ---- issue ALL prefetch loads for chunk c+1 ----
        if (c + 1 < NC) {
            size_t tbase1 = ((size_t)(c+1)*CH*NH + h)*HD;
#pragma unroll
            for (int i = 0; i < 4; ++i) {
                size_t go = tbase1 + (size_t)stt[i]*ROW + sk4[i];
                rKb[i] = *(const float4*)(gg + go);
                rQt[i] = *(const float4*)(gq + go);
                rKr[i] = *(const float4*)(gk + go);
            }
            size_t mbase1 = (size_t)((c+1)*NH + h) * CH * CH;
#pragma unroll
            for (int i = 0; i < 2; ++i)
                rM[i] = *(const float4*)(gM + mbase1 + mtt[i]*64 + ms4[i]);
            if (tid < 256)
                rVb = *(const float4*)(gv + tbase1 + (size_t)vtt*ROW + j0 + vj4);
            if (tid < HD) rCp = gCp[((c+1)*NH+h)*HD + tid];
        }

        // ---- fused: D-partial = (g? 0 : Vb) - Kb@S_half, X-partial = Qt@S_half
        {
            float4 dA, xA;
            if (g == 0) dA = *(const float4*)(VbS + id*4);
            else        dA = make_float4(0.f,0.f,0.f,0.f);
            xA = make_float4(0.f,0.f,0.f,0.f);
            const float* kbr = KbS + t*ST3 + k0;
            const float* qtr = QtS + t*ST3 + k0;
            const float* Sp  = S + k0*16 + jq*4;
#pragma unroll 4
            for (int k = 0; k < 64; ++k) {
                float kb = kbr[k], qv = qtr[k];
                float4 sv = *(const float4*)(Sp + k*16);
                dA.x -= kb*sv.x; dA.y -= kb*sv.y; dA.z -= kb*sv.z; dA.w -= kb*sv.w;
                xA.x += qv*sv.x; xA.y += qv*sv.y; xA.z += qv*sv.z; xA.w += qv*sv.w;
            }
            if (g == 0) { *(float4*)(DS1 + id*4) = dA; *(float4*)(XS1 + id*4) = xA; }
            else        { *(float4*)(DS2 + id*4) = dA; *(float4*)(XS2 + id*4) = xA; }
        }
        __syncthreads();   // sync1: partials ready; Kb/Qt/Vb/S free for this phase

        // ---- group1 commit (c+1): KbS, QtS, VbS ----
        if (c + 1 < NC) {
#pragma unroll
            for (int i = 0; i < 4; ++i) {
                *(float4*)(KbS + stt[i]*ST3 + sk4[i]) = rKb[i];
                *(float4*)(QtS + stt[i]*ST3 + sk4[i]) = rQt[i];
            }
            if (tid < 256) *(float4*)(VbS + vtt*16 + vj4) = rVb;
        }

        // ---- combine partials: warps 0-7 -> D, warps 8-15 -> X ----
        {
            float* A = (tid < 256) ? DS1 : XS1;
            float* B = (tid < 256) ? DS2 : XS2;
            float4 a = *(const float4*)(A + id*4);
            float4 b = *(const float4*)(B + id*4);
            a.x += b.x; a.y += b.y; a.z += b.z; a.w += b.w;
            *(float4*)(A + id*4) = a;
        }
        __syncthreads();   // sync2: D, X final

        if (tid < 256) {
            // ---- O = X + M@D (triangular: M[t][s>t]==0, warp-uniform bound) ----
            float4 o = *(const float4*)(XS1 + id*4);
            const float* mr = MS + t*MT3;
            int bound = (t & ~7) + 8;
            for (int s = 0; s < bound; ++s) {
                float mv = mr[s];
                float4 dv = *(const float4*)(DS1 + s*16 + jq*4);
                o.x += mv*dv.x; o.y += mv*dv.y; o.z += mv*dv.z; o.w += mv*dv.w;
            }
            *(float4*)(out + ((size_t)(c*CH + t)*NH + h)*HD + j0 + jq*4) = o;
        } else {
            // ---- S = cp.*S + Kbar^T@D  (2 k-rows x 4 cols per thread) ----
            int kr2 = id >> 2, jq2 = id & 3;
            float ca = cpS[kr2], cb = cpS[kr2 + 64];
            float4 sa = *(const float4*)(S + kr2*16 + jq2*4);
            float4 sb = *(const float4*)(S + (kr2+64)*16 + jq2*4);
            sa.x *= ca; sa.y *= ca; sa.z *= ca; sa.w *= ca;
            sb.x *= cb; sb.y *= cb; sb.z *= cb; sb.w *= cb;
            const float* kra = KrS + kr2;
#pragma unroll 4
            for (int s = 0; s < CH; ++s) {
                float ka  = kra[s*ST3];
                float kb2 = kra[s*ST3 + 64];
                float4 dv = *(const float4*)(DS1 + s*16 + jq2*4);
                sa.x += ka*dv.x;  sa.y += ka*dv.y;  sa.z += ka*dv.z;  sa.w += ka*dv.w;
                sb.x += kb2*dv.x; sb.y += kb2*dv.y; sb.z += kb2*dv.z; sb.w += kb2*dv.w;
            }
            *(float4*)(S + kr2*16 + jq2*4)      = sa;
            *(float4*)(S + (kr2+64)*16 + jq2*4) = sb;
        }
        __syncthreads();   // sync3: S updated; KrS/MS/cpS free to overwrite

        // ---- group2 commit (c+1): KrS, MS, cpS — overlaps next fused pass ----
        if (c + 1 < NC) {
#pragma unroll
            for (int i = 0; i < 4; ++i)
                *(float4*)(KrS + stt[i]*ST3 + sk4[i]) = rKr[i];
#pragma unroll
            for (int i = 0; i < 2; ++i)
                *(float4*)(MS + mtt[i]*MT3 + ms4[i]) = rM[i];
            if (tid < HD) cpS[tid] = rCp;
        }
        // no sync here: group2 arrays are next read only after next sync2.
    }
}

// =========================================================================
extern "C" void kernel_launch(void* const* d_in, const int* in_sizes, int n_in,
                              void* d_out, int out_size)
{
    (void)in_sizes; (void)n_in; (void)out_size;
    const float* qkv  = (const float*)d_in[0];
    const float* fg   = (const float*)d_in[1];
    const float* beta = (const float*)d_in[2];
    const float* cw   = (const float*)d_in[3];
    const float* dtb  = (const float*)d_in[4];
    const float* alog = (const float*)d_in[5];
    float* out = (float*)d_out;

    int smem12 = (4*CH*P2S + CH*65 + 64) * 4;                              // 152,064
    int smem3  = (3*CH*ST3 + CH*MT3 + 5*1024 + HD + HD*16) * 4;            // 147,968
    cudaFuncSetAttribute(k_phase12, cudaFuncAttributeMaxDynamicSharedMemorySize, smem12);
    cudaFuncSetAttribute(k_phase3,  cudaFuncAttributeMaxDynamicSharedMemorySize, smem3);

    k_phase12<<<dim3(NC, NH), 512, smem12>>>(qkv, fg, beta, cw, dtb, alog);
    k_phase3<<<dim3(8, NH), 512, smem3>>>(out);
}

// round 14
// speedup vs baseline: 1.0510x; 1.0510x over previous
#include <cuda_runtime.h>
#include <math.h>

#define T_TOK 8192
#define NH 16
#define HD 128
#define CH 64
#define NC 128
#define ROW (NH*HD)   // 2048

// ------------------- device scratch (allocation-free) -------------------
__device__ float gq [T_TOK*ROW];   // q~   (phase12 out)
__device__ float gk [T_TOK*ROW];   // Kbar
__device__ float gv [T_TOK*ROW];   // Vb
__device__ float gg [T_TOK*ROW];   // Kb
__device__ float gM [NC*NH*CH*CH];
__device__ float gCp[NC*NH*HD];

// =========================================================================
// Phase 1+2 fused (FROZEN from R11/R12): conv+SiLU+l2norm+gates in smem,
// cumsum / transform / pair matrices / blocked forward substitution.
// grid (NC, NH), block 512, dyn smem ~149 KB
// =========================================================================
#define P2S 132   // padded row stride (float4-aligned)

__global__ void __launch_bounds__(512) k_phase12(
    const float* __restrict__ qkv, const float* __restrict__ fg,
    const float* __restrict__ beta, const float* __restrict__ cw,
    const float* __restrict__ dtb, const float* __restrict__ alog)
{
    extern __shared__ float sm[];
    float* gcS = sm;               // 64*132 (gates -> cumsum -> ZB = Kb)
    float* qS  = gcS + CH*P2S;     // 64*132 (q -> ZA = Vb)
    float* kS  = qS  + CH*P2S;     // 64*132
    float* vS  = kS  + CH*P2S;     // 64*132
    float* Ls  = vS  + CH*P2S;     // 64*65
    float* bS  = Ls  + CH*65;      // 64

    int c = blockIdx.x, h = blockIdx.y, tid = threadIdx.x;
    int w = tid >> 5, l = tid & 31;
    size_t tbase = ((size_t)c*CH*NH + h)*HD;

    // ================= step A: conv(K=4)+SiLU+l2norm+gates ================
    {
        int tloc0 = w * 4;                    // 4 tokens per warp
        int t0 = c * CH + tloc0;
        int d0 = l * 4;
        int cq = h*HD + d0, ck = ROW + cq, cv = 2*ROW + cq;

        float wq[4][4], wk[4][4], wv[4][4];
#pragma unroll
        for (int e = 0; e < 4; ++e)
#pragma unroll
            for (int j = 0; j < 4; ++j) {
                wq[e][j] = cw[(cq+e)*4 + j];
                wk[e][j] = cw[(ck+e)*4 + j];
                wv[e][j] = cw[(cv+e)*4 + j];
            }
        float ea = expf(alog[h]);
        float dtv[4];
        *(float4*)dtv = *(const float4*)(dtb + h*HD + d0);

        float pq[3][4], pk[3][4], pv[3][4];
#pragma unroll
        for (int j = 0; j < 3; ++j) {
            int ts = t0 - 3 + j;
            if (ts >= 0) {
                const float* row = qkv + (size_t)ts * (3*ROW);
                *(float4*)pq[j] = *(const float4*)(row + cq);
                *(float4*)pk[j] = *(const float4*)(row + ck);
                *(float4*)pv[j] = *(const float4*)(row + cv);
            } else {
#pragma unroll
                for (int e = 0; e < 4; ++e) { pq[j][e]=0.f; pk[j][e]=0.f; pv[j][e]=0.f; }
            }
        }

#pragma unroll
        for (int tt = 0; tt < 4; ++tt) {
            int t = t0 + tt, tloc = tloc0 + tt;
            const float* row = qkv + (size_t)t * (3*ROW);
            float rq[4], rk[4], rv[4], fgv[4];
            *(float4*)rq = *(const float4*)(row + cq);
            *(float4*)rk = *(const float4*)(row + ck);
            *(float4*)rv = *(const float4*)(row + cv);
            *(float4*)fgv = *(const float4*)(fg + (size_t)t*ROW + h*HD + d0);

            float xq[4], xk[4], xv[4];
#pragma unroll
            for (int e = 0; e < 4; ++e) {
                float aq = pq[0][e]*wq[e][0] + pq[1][e]*wq[e][1] + pq[2][e]*wq[e][2] + rq[e]*wq[e][3];
                float ak = pk[0][e]*wk[e][0] + pk[1][e]*wk[e][1] + pk[2][e]*wk[e][2] + rk[e]*wk[e][3];
                float av = pv[0][e]*wv[e][0] + pv[1][e]*wv[e][1] + pv[2][e]*wv[e][2] + rv[e]*wv[e][3];
                xq[e] = aq / (1.f + __expf(-aq));
                xk[e] = ak / (1.f + __expf(-ak));
                xv[e] = av / (1.f + __expf(-av));
            }
#pragma unroll
            for (int j = 0; j < 2; ++j)
#pragma unroll
                for (int e = 0; e < 4; ++e) { pq[j][e]=pq[j+1][e]; pk[j][e]=pk[j+1][e]; pv[j][e]=pv[j+1][e]; }
#pragma unroll
            for (int e = 0; e < 4; ++e) { pq[2][e]=rq[e]; pk[2][e]=rk[e]; pv[2][e]=rv[e]; }

            float sq = xq[0]*xq[0]+xq[1]*xq[1]+xq[2]*xq[2]+xq[3]*xq[3];
            float sk = xk[0]*xk[0]+xk[1]*xk[1]+xk[2]*xk[2]+xk[3]*xk[3];
#pragma unroll
            for (int m = 16; m; m >>= 1) {
                sq += __shfl_xor_sync(~0u, sq, m);
                sk += __shfl_xor_sync(~0u, sk, m);
            }
            float rnq = rsqrtf(sq + 1e-6f) * 0.08838834764831845f; // * D^-1/2
            float rnk = rsqrtf(sk + 1e-6f);

            float oq[4], ok[4], og[4];
#pragma unroll
            for (int e = 0; e < 4; ++e) {
                oq[e] = xq[e] * rnq;
                ok[e] = xk[e] * rnk;
                float gr = fgv[e] + dtv[e];
                float sp = (gr > 20.f) ? gr : log1pf(__expf(gr));
                og[e] = -ea * sp;
            }
            *(float4*)(qS  + tloc*P2S + d0) = *(float4*)oq;
            *(float4*)(kS  + tloc*P2S + d0) = *(float4*)ok;
            *(float4*)(vS  + tloc*P2S + d0) = *(float4*)xv;
            *(float4*)(gcS + tloc*P2S + d0) = *(float4*)og;
            if (l == 0) {
                float bb = beta[t*NH + h];
                bS[tloc] = 1.f / (1.f + __expf(-bb));
            }
        }
    }
    __syncthreads();

    // ---- gc cumsum over t ----
    if (tid < HD) {
        float run = 0.f;
        for (int t = 0; t < CH; ++t) { run += gcS[t*P2S+tid]; gcS[t*P2S+tid] = run; }
    }
    __syncthreads();

    // ---- q~ = q*exp(gc), Kbar = k*exp(gc63-gc), cp = exp(gc63) ----
    for (int i = tid; i < CH*HD; i += 512) {
        int t = i >> 7, k = i & 127;
        float gct = gcS[t*P2S+k];
        float g63 = gcS[63*P2S+k];
        size_t go = tbase + (size_t)t*ROW + k;
        gq[go] = qS[t*P2S+k] * __expf(gct);
        gk[go] = kS[t*P2S+k] * __expf(g63 - gct);
    }
    if (tid < HD) gCp[(c*NH+h)*HD + tid] = __expf(gcS[63*P2S+tid]);

    // ---- pair tiles: warp processes an 8t x 4s tile, lane=(tr,sc) ----
    size_t mbase = (size_t)(c*NH + h) * CH * CH;
    {
        int l5 = tid & 31, tr = l5 >> 2, sc = l5 & 3;
        for (int tile = w; tile < 72; tile += 16) {
            int i = 0;
            while ((i+1)*(i+2) <= tile) ++i;    // tiles before row i = i*(i+1)
            int j = tile - i*(i+1);
            int t = i*8 + tr, s = j*4 + sc;
            const float* gtr = gcS + t*P2S; const float* gsr = gcS + s*P2S;
            const float* ktr = kS  + t*P2S; const float* ksr = kS  + s*P2S;
            const float* qtr = qS  + t*P2S;
            float a = 0.f, m = 0.f;
#pragma unroll 4
            for (int k = 0; k < HD; k += 4) {
                float4 g1 = *(const float4*)(gtr + k);
                float4 g0 = *(const float4*)(gsr + k);
                float4 kt4 = *(const float4*)(ktr + k);
                float4 ks4 = *(const float4*)(ksr + k);
                float4 qt4 = *(const float4*)(qtr + k);
                float e, kv;
                e = __expf(g1.x - g0.x); kv = ks4.x * e; a += kt4.x*kv; m += qt4.x*kv;
                e = __expf(g1.y - g0.y); kv = ks4.y * e; a += kt4.y*kv; m += qt4.y*kv;
                e = __expf(g1.z - g0.z); kv = ks4.z * e; a += kt4.z*kv; m += qt4.z*kv;
                e = __expf(g1.w - g0.w); kv = ks4.w * e; a += kt4.w*kv; m += qt4.w*kv;
            }
            if (s <= t) gM[mbase + t*64 + s] = m;
            if (s <  t) Ls[t*65 + s] = bS[t] * a;
        }
    }
    // zero upper triangle of M (phase3 relies on M[t][s>t] == 0)
    for (int i = tid; i < 4096; i += 512) {
        int t = i >> 6, s = i & 63;
        if (s > t) gM[mbase + i] = 0.f;
    }
    __syncthreads();

    // ---- RHS in place: ZA(qS) = b*v, ZB(gcS) = b*k*exp(gc) ----
    for (int i = tid; i < CH*HD; i += 512) {
        int t = i >> 7, k = i & 127;
        float bb = bS[t];
        float zb = bb * kS[t*P2S+k] * __expf(gcS[t*P2S+k]);
        qS [t*P2S+k] = bb * vS[t*P2S+k];
        gcS[t*P2S+k] = zb;
    }
    __syncthreads();

    // ---- blocked forward substitution (I+L) Z = RHS ----
#pragma unroll
    for (int ib = 0; ib < 4; ++ib) {
        int i0 = ib * 16;
        if (tid < 256) {
            float* Z = (tid < 128) ? (qS + tid) : (gcS + (tid - 128));
            for (int t = i0+1; t < i0+16; ++t) {
                float acc = 0.f;
                const float* lrow = Ls + t*65;
                for (int s = i0; s < t; ++s) acc += lrow[s] * Z[s*P2S];
                Z[t*P2S] -= acc;
            }
        }
        __syncthreads();
        int rows = 48 - 16*ib;
        if (rows > 0) {
            int slots = rows * 128;
            for (int sl = tid; sl < slots; sl += 512) {
                int t  = i0 + 16 + (sl >> 7);
                int c2 = sl & 127;
                float* Z = (c2 < 64) ? (qS + c2*2) : (gcS + (c2-64)*2);
                float2 acc = make_float2(0.f, 0.f);
                const float* lrow = Ls + t*65 + i0;
#pragma unroll
                for (int s = 0; s < 16; ++s) {
                    float lv = lrow[s];
                    float2 zv = *(const float2*)(Z + (i0+s)*P2S);
                    acc.x += lv*zv.x; acc.y += lv*zv.y;
                }
                float2 zt = *(float2*)(Z + t*P2S);
                zt.x -= acc.x; zt.y -= acc.y;
                *(float2*)(Z + t*P2S) = zt;
            }
        }
        __syncthreads();
    }

    // ---- write out: Vb -> gv, Kb -> gg ----
    for (int i = tid; i < CH*HD; i += 512) {
        int t = i >> 7, k = i & 127;
        size_t go = tbase + (size_t)t*ROW + k;
        gv[go] = qS [t*P2S+k];
        gg[go] = gcS[t*P2S+k];
    }
}

// =========================================================================
// Phase 3: sequential chunk scan, 1024 threads (occ 50%), 4-way split-K
// fused pass, O-pass || S-update, register-prefetched staging.
// grid (8, NH) = 128 blocks.
// =========================================================================
#define ST3 132          // k-row stride (float4-aligned)
#define MT3 68           // M row stride

__global__ void __launch_bounds__(1024) k_phase3(float* __restrict__ out)
{
    extern __shared__ float sm[];
    float* KbS = sm;                 // 64*132
    float* QtS = KbS + CH*ST3;
    float* KrS = QtS + CH*ST3;
    float* MS  = KrS + CH*ST3;       // 64*68
    float* VbS = MS  + CH*MT3;       // 1024
    float* DS0 = VbS + 1024;         // 4 x 1024 D partials (DS0 = final)
    float* XS0 = DS0 + 4*1024;       // 4 x 1024 X partials (XS0 = final)
    float* cpS = XS0 + 4*1024;       // 128
    float* S   = cpS + HD;           // 128*16

    int h = blockIdx.y, j0 = blockIdx.x * 16, tid = threadIdx.x;
    int kq = tid >> 8;               // k-quarter 0..3
    int id = tid & 255;
    int t  = id >> 2, jq = id & 3;   // (t, j-quad)
    int k0 = kq * 32;

    // staging maps: 2 rows/thread for big tiles, 1 float4 for M, etc.
    float4 rKb[2], rQt[2], rKr[2], rM, rVb;
    float rCp = 0.f;
    int stt[2], sk4[2];
#pragma unroll
    for (int i = 0; i < 2; ++i) {
        int idx = tid + i*1024;
        stt[i] = idx >> 5; sk4[i] = (idx & 31) * 4;
    }
    int mtt = tid >> 4, ms4 = (tid & 15) * 4;
    int vtt = tid >> 2, vj4 = (tid & 3) * 4;

    for (int i = tid; i < HD*16; i += 1024) S[i] = 0.f;

    // ---- prologue: stage chunk 0 directly ----
    {
        size_t tbase = ((size_t)h)*HD;
#pragma unroll
        for (int i = 0; i < 2; ++i) {
            size_t go = tbase + (size_t)stt[i]*ROW + sk4[i];
            *(float4*)(KbS + stt[i]*ST3 + sk4[i]) = *(const float4*)(gg + go);
            *(float4*)(QtS + stt[i]*ST3 + sk4[i]) = *(const float4*)(gq + go);
            *(float4*)(KrS + stt[i]*ST3 + sk4[i]) = *(const float4*)(gk + go);
        }
        *(float4*)(MS + mtt*MT3 + ms4) =
            *(const float4*)(gM + (size_t)h*CH*CH + mtt*64 + ms4);
        if (tid < 256)
            *(float4*)(VbS + vtt*16 + vj4) =
                *(const float4*)(gv + tbase + (size_t)vtt*ROW + j0 + vj4);
        if (tid < HD) cpS[tid] = gCp[h*HD + tid];
    }
    __syncthreads();

    for (int c = 0; c < NC; ++c) {
        // ---- prefetch chunk c+1 into registers ----
        if (c + 1 < NC) {
            size_t tbase1 = ((size_t)(c+1)*CH*NH + h)*HD;
#pragma unroll
            for (int i = 0; i < 2; ++i) {
                size_t go = tbase1 + (size_t)stt[i]*ROW + sk4[i];
                rKb[i] = *(const float4*)(gg + go);
                rQt[i] = *(const float4*)(gq + go);
                rKr[i] = *(const float4*)(gk + go);
            }
            rM = *(const float4*)(gM + (size_t)((c+1)*NH + h)*CH*CH + mtt*64 + ms4);
            if (tid < 256)
                rVb = *(const float4*)(gv + tbase1 + (size_t)vtt*ROW + j0 + vj4);
            if (tid < HD) rCp = gCp[((c+1)*NH+h)*HD + tid];
        }

        // ---- fused split-K: D-part = (kq0? Vb:0) - Kb@S_q, X-part = Qt@S_q --
        {
            float4 dA, xA;
            if (kq == 0) dA = *(const float4*)(VbS + id*4);
            else         dA = make_float4(0.f,0.f,0.f,0.f);
            xA = make_float4(0.f,0.f,0.f,0.f);
            const float* kbr = KbS + t*ST3 + k0;
            const float* qtr = QtS + t*ST3 + k0;
            const float* Sp  = S + k0*16 + jq*4;
#pragma unroll 4
            for (int k = 0; k < 32; ++k) {
                float kb = kbr[k], qv = qtr[k];
                float4 sv = *(const float4*)(Sp + k*16);
                dA.x -= kb*sv.x; dA.y -= kb*sv.y; dA.z -= kb*sv.z; dA.w -= kb*sv.w;
                xA.x += qv*sv.x; xA.y += qv*sv.y; xA.z += qv*sv.z; xA.w += qv*sv.w;
            }
            *(float4*)(DS0 + kq*1024 + id*4) = dA;
            *(float4*)(XS0 + kq*1024 + id*4) = xA;
        }
        __syncthreads();   // sync1: partials ready; KbS/QtS/VbS/S idle now

        // ---- commit group1 (c+1): KbS, QtS, VbS (all threads) ----
        if (c + 1 < NC) {
#pragma unroll
            for (int i = 0; i < 2; ++i) {
                *(float4*)(KbS + stt[i]*ST3 + sk4[i]) = rKb[i];
                *(float4*)(QtS + stt[i]*ST3 + sk4[i]) = rQt[i];
            }
            if (tid < 256) *(float4*)(VbS + vtt*16 + vj4) = rVb;
        }
        // ---- combine partials: 256 thr -> D, 256 thr -> X ----
        if (tid < 512) {
            float* A = (tid < 256) ? DS0 : XS0;
            int i4 = (tid & 255) * 4;
            float4 a = *(const float4*)(A + i4);
            float4 b = *(const float4*)(A + 1024 + i4);
            float4 d = *(const float4*)(A + 2048 + i4);
            float4 e = *(const float4*)(A + 3072 + i4);
            a.x += b.x + d.x + e.x; a.y += b.y + d.y + e.y;
            a.z += b.z + d.z + e.z; a.w += b.w + d.w + e.w;
            *(float4*)(A + i4) = a;
        }
        __syncthreads();   // sync2: D (DS0), X (XS0) final

        if (tid < 256) {
            // ---- O = X + M@D (M upper triangle zero; warp-uniform bound) ----
            float4 o = *(const float4*)(XS0 + id*4);
            const float* mr = MS + t*MT3;
            int bound = (t & ~7) + 8;
            for (int s = 0; s < bound; ++s) {
                float mv = mr[s];
                float4 dv = *(const float4*)(DS0 + s*16 + jq*4);
                o.x += mv*dv.x; o.y += mv*dv.y; o.z += mv*dv.z; o.w += mv*dv.w;
            }
            *(float4*)(out + ((size_t)(c*CH + t)*NH + h)*HD + j0 + jq*4) = o;
        } else if (tid < 768) {
            // ---- S = cp.*S + Kbar^T@D  (one k-row x float4 per thread) ----
            int u = tid - 256;
            int krow = u >> 2, jq2 = u & 3;
            float cp = cpS[krow];
            float4 sa = *(const float4*)(S + krow*16 + jq2*4);
            sa.x *= cp; sa.y *= cp; sa.z *= cp; sa.w *= cp;
            const float* kra = KrS + krow;
#pragma unroll 4
            for (int s = 0; s < CH; ++s) {
                float ka = kra[s*ST3];
                float4 dv = *(const float4*)(DS0 + s*16 + jq2*4);
                sa.x += ka*dv.x; sa.y += ka*dv.y; sa.z += ka*dv.z; sa.w += ka*dv.w;
            }
            *(float4*)(S + krow*16 + jq2*4) = sa;
        }
        __syncthreads();   // sync3: S updated; KrS/MS/cpS free

        // ---- commit group2 (c+1): KrS, MS, cpS ----
        if (c + 1 < NC) {
#pragma unroll
            for (int i = 0; i < 2; ++i)
                *(float4*)(KrS + stt[i]*ST3 + sk4[i]) = rKr[i];
            *(float4*)(MS + mtt*MT3 + ms4) = rM;
            if (tid < HD) cpS[tid] = rCp;
        }
        // no sync: group2 arrays are next read only after next sync2
        // (O-pass/S-update), with sync1+sync2 in between on every thread.
    }
}

// =========================================================================
extern "C" void kernel_launch(void* const* d_in, const int* in_sizes, int n_in,
                              void* d_out, int out_size)
{
    (void)in_sizes; (void)n_in; (void)out_size;
    const float* qkv  = (const float*)d_in[0];
    const float* fg   = (const float*)d_in[1];
    const float* beta = (const float*)d_in[2];
    const float* cw   = (const float*)d_in[3];
    const float* dtb  = (const float*)d_in[4];
    const float* alog = (const float*)d_in[5];
    float* out = (float*)d_out;

    int smem12 = (4*CH*P2S + CH*65 + 64) * 4;                              // 152,064
    int smem3  = (3*CH*ST3 + CH*MT3 + 1024 + 8*1024 + HD + HD*16) * 4;     // 164,352
    cudaFuncSetAttribute(k_phase12, cudaFuncAttributeMaxDynamicSharedMemorySize, smem12);
    cudaFuncSetAttribute(k_phase3,  cudaFuncAttributeMaxDynamicSharedMemorySize, smem3);

    k_phase12<<<dim3(NC, NH), 512, smem12>>>(qkv, fg, beta, cw, dtb, alog);
    k_phase3<<<dim3(8, NH), 1024, smem3>>>(out);
}

// round 15
// speedup vs baseline: 1.2402x; 1.1801x over previous
#include <cuda_runtime.h>
#include <math.h>

#define T_TOK 8192
#define NH 16
#define HD 128
#define CH 64
#define NC 128
#define ROW (NH*HD)   // 2048

// ------------------- device scratch (allocation-free) -------------------
__device__ float gq [T_TOK*ROW];   // q~   (phase12 out)
__device__ float gk [T_TOK*ROW];   // Kbar
__device__ float gv [T_TOK*ROW];   // raw v (step A) -> Vb (phase12 out)
__device__ float gg [T_TOK*ROW];   // Kb
__device__ float gM [NC*NH*CH*CH];
__device__ float gCp[NC*NH*HD];

// =========================================================================
// Phase 1+2 fused, 2 blocks/SM: step A in 3 register-lean passes (q/k/v),
// v via global round-trip, Ls triangular-packed. grid (NC, NH), block 512.
// =========================================================================
#define P2S 132   // padded row stride (float4-aligned)

__global__ void __launch_bounds__(512, 2) k_phase12(
    const float* __restrict__ qkv, const float* __restrict__ fg,
    const float* __restrict__ beta, const float* __restrict__ cw,
    const float* __restrict__ dtb, const float* __restrict__ alog)
{
    extern __shared__ float sm[];
    float* gcS = sm;               // 64*132 (gates -> cumsum -> ZB = Kb)
    float* qS  = gcS + CH*P2S;     // 64*132 (q -> ZA = Vb)
    float* kS  = qS  + CH*P2S;     // 64*132
    float* Ls  = kS  + CH*P2S;     // 2080 (triangular packed)
    float* bS  = Ls  + 2080;       // 64

    int c = blockIdx.x, h = blockIdx.y, tid = threadIdx.x;
    int w = tid >> 5, l = tid & 31;
    size_t tbase = ((size_t)c*CH*NH + h)*HD;

    int tloc0 = w * 4;             // 4 tokens per warp
    int t0g = c * CH + tloc0;
    int d0 = l * 4;

    // ================= step A pass 1: q =================
    {
        int cx = h*HD + d0;
        float wx[4][4];
#pragma unroll
        for (int e = 0; e < 4; ++e)
#pragma unroll
            for (int j = 0; j < 4; ++j) wx[e][j] = cw[(cx+e)*4 + j];
        float px[3][4];
#pragma unroll
        for (int j = 0; j < 3; ++j) {
            int ts = t0g - 3 + j;
            if (ts >= 0) *(float4*)px[j] = *(const float4*)(qkv + (size_t)ts*(3*ROW) + cx);
            else { px[j][0]=px[j][1]=px[j][2]=px[j][3]=0.f; }
        }
#pragma unroll
        for (int tt = 0; tt < 4; ++tt) {
            int t = t0g + tt, tloc = tloc0 + tt;
            float rx[4];
            *(float4*)rx = *(const float4*)(qkv + (size_t)t*(3*ROW) + cx);
            float xx[4];
#pragma unroll
            for (int e = 0; e < 4; ++e) {
                float a = px[0][e]*wx[e][0] + px[1][e]*wx[e][1] + px[2][e]*wx[e][2] + rx[e]*wx[e][3];
                xx[e] = a / (1.f + __expf(-a));
            }
#pragma unroll
            for (int j = 0; j < 2; ++j)
#pragma unroll
                for (int e = 0; e < 4; ++e) px[j][e] = px[j+1][e];
#pragma unroll
            for (int e = 0; e < 4; ++e) px[2][e] = rx[e];
            float s2 = xx[0]*xx[0]+xx[1]*xx[1]+xx[2]*xx[2]+xx[3]*xx[3];
#pragma unroll
            for (int m = 16; m; m >>= 1) s2 += __shfl_xor_sync(~0u, s2, m);
            float rn = rsqrtf(s2 + 1e-6f) * 0.08838834764831845f;  // * D^-1/2
            float ox[4];
#pragma unroll
            for (int e = 0; e < 4; ++e) ox[e] = xx[e] * rn;
            *(float4*)(qS + tloc*P2S + d0) = *(float4*)ox;
        }
    }
    // ================= step A pass 2: k =================
    {
        int cx = ROW + h*HD + d0;
        float wx[4][4];
#pragma unroll
        for (int e = 0; e < 4; ++e)
#pragma unroll
            for (int j = 0; j < 4; ++j) wx[e][j] = cw[(cx+e)*4 + j];
        float px[3][4];
#pragma unroll
        for (int j = 0; j < 3; ++j) {
            int ts = t0g - 3 + j;
            if (ts >= 0) *(float4*)px[j] = *(const float4*)(qkv + (size_t)ts*(3*ROW) + cx);
            else { px[j][0]=px[j][1]=px[j][2]=px[j][3]=0.f; }
        }
#pragma unroll
        for (int tt = 0; tt < 4; ++tt) {
            int t = t0g + tt, tloc = tloc0 + tt;
            float rx[4];
            *(float4*)rx = *(const float4*)(qkv + (size_t)t*(3*ROW) + cx);
            float xx[4];
#pragma unroll
            for (int e = 0; e < 4; ++e) {
                float a = px[0][e]*wx[e][0] + px[1][e]*wx[e][1] + px[2][e]*wx[e][2] + rx[e]*wx[e][3];
                xx[e] = a / (1.f + __expf(-a));
            }
#pragma unroll
            for (int j = 0; j < 2; ++j)
#pragma unroll
                for (int e = 0; e < 4; ++e) px[j][e] = px[j+1][e];
#pragma unroll
            for (int e = 0; e < 4; ++e) px[2][e] = rx[e];
            float s2 = xx[0]*xx[0]+xx[1]*xx[1]+xx[2]*xx[2]+xx[3]*xx[3];
#pragma unroll
            for (int m = 16; m; m >>= 1) s2 += __shfl_xor_sync(~0u, s2, m);
            float rn = rsqrtf(s2 + 1e-6f);
            float ox[4];
#pragma unroll
            for (int e = 0; e < 4; ++e) ox[e] = xx[e] * rn;
            *(float4*)(kS + tloc*P2S + d0) = *(float4*)ox;
        }
    }
    // ================= step A pass 3: v (global) + gates =================
    {
        int cx = 2*ROW + h*HD + d0;
        float wx[4][4];
#pragma unroll
        for (int e = 0; e < 4; ++e)
#pragma unroll
            for (int j = 0; j < 4; ++j) wx[e][j] = cw[(cx+e)*4 + j];
        float ea = expf(alog[h]);
        float dtv[4];
        *(float4*)dtv = *(const float4*)(dtb + h*HD + d0);
        float px[3][4];
#pragma unroll
        for (int j = 0; j < 3; ++j) {
            int ts = t0g - 3 + j;
            if (ts >= 0) *(float4*)px[j] = *(const float4*)(qkv + (size_t)ts*(3*ROW) + cx);
            else { px[j][0]=px[j][1]=px[j][2]=px[j][3]=0.f; }
        }
#pragma unroll
        for (int tt = 0; tt < 4; ++tt) {
            int t = t0g + tt, tloc = tloc0 + tt;
            float rx[4], fgv[4];
            *(float4*)rx = *(const float4*)(qkv + (size_t)t*(3*ROW) + cx);
            *(float4*)fgv = *(const float4*)(fg + (size_t)t*ROW + h*HD + d0);
            float xx[4], og[4];
#pragma unroll
            for (int e = 0; e < 4; ++e) {
                float a = px[0][e]*wx[e][0] + px[1][e]*wx[e][1] + px[2][e]*wx[e][2] + rx[e]*wx[e][3];
                xx[e] = a / (1.f + __expf(-a));
                float gr = fgv[e] + dtv[e];
                float sp = (gr > 20.f) ? gr : log1pf(__expf(gr));
                og[e] = -ea * sp;
            }
#pragma unroll
            for (int j = 0; j < 2; ++j)
#pragma unroll
                for (int e = 0; e < 4; ++e) px[j][e] = px[j+1][e];
#pragma unroll
            for (int e = 0; e < 4; ++e) px[2][e] = rx[e];
            *(float4*)(gv + tbase + (size_t)tloc*ROW + d0) = *(float4*)xx;   // raw v
            *(float4*)(gcS + tloc*P2S + d0) = *(float4*)og;
            if (l == 0) {
                float bb = beta[t*NH + h];
                bS[tloc] = 1.f / (1.f + __expf(-bb));
            }
        }
    }
    __syncthreads();

    // ---- gc cumsum over t ----
    if (tid < HD) {
        float run = 0.f;
        for (int t = 0; t < CH; ++t) { run += gcS[t*P2S+tid]; gcS[t*P2S+tid] = run; }
    }
    __syncthreads();

    // ---- q~ = q*exp(gc), Kbar = k*exp(gc63-gc), cp = exp(gc63) ----
    for (int i = tid; i < CH*HD; i += 512) {
        int t = i >> 7, k = i & 127;
        float gct = gcS[t*P2S+k];
        float g63 = gcS[63*P2S+k];
        size_t go = tbase + (size_t)t*ROW + k;
        gq[go] = qS[t*P2S+k] * __expf(gct);
        gk[go] = kS[t*P2S+k] * __expf(g63 - gct);
    }
    if (tid < HD) gCp[(c*NH+h)*HD + tid] = __expf(gcS[63*P2S+tid]);

    // ---- pair tiles: warp processes an 8t x 4s tile, lane=(tr,sc) ----
    size_t mbase = (size_t)(c*NH + h) * CH * CH;
    {
        int l5 = tid & 31, tr = l5 >> 2, sc = l5 & 3;
        for (int tile = w; tile < 72; tile += 16) {
            int i = 0;
            while ((i+1)*(i+2) <= tile) ++i;    // tiles before row i = i*(i+1)
            int j = tile - i*(i+1);
            int t = i*8 + tr, s = j*4 + sc;
            const float* gtr = gcS + t*P2S; const float* gsr = gcS + s*P2S;
            const float* ktr = kS  + t*P2S; const float* ksr = kS  + s*P2S;
            const float* qtr = qS  + t*P2S;
            float a = 0.f, m = 0.f;
#pragma unroll 4
            for (int k = 0; k < HD; k += 4) {
                float4 g1 = *(const float4*)(gtr + k);
                float4 g0 = *(const float4*)(gsr + k);
                float4 kt4 = *(const float4*)(ktr + k);
                float4 ks4 = *(const float4*)(ksr + k);
                float4 qt4 = *(const float4*)(qtr + k);
                float e, kv;
                e = __expf(g1.x - g0.x); kv = ks4.x * e; a += kt4.x*kv; m += qt4.x*kv;
                e = __expf(g1.y - g0.y); kv = ks4.y * e; a += kt4.y*kv; m += qt4.y*kv;
                e = __expf(g1.z - g0.z); kv = ks4.z * e; a += kt4.z*kv; m += qt4.z*kv;
                e = __expf(g1.w - g0.w); kv = ks4.w * e; a += kt4.w*kv; m += qt4.w*kv;
            }
            if (s <= t) gM[mbase + t*64 + s] = m;
            if (s <  t) Ls[(t*(t+1))/2 + s] = bS[t] * a;
        }
    }
    // zero upper triangle of M (phase3 relies on M[t][s>t] == 0)
    for (int i = tid; i < 4096; i += 512) {
        int t = i >> 6, s = i & 63;
        if (s > t) gM[mbase + i] = 0.f;
    }
    __syncthreads();

    // ---- RHS in place: ZA(qS) = b*v (from gv), ZB(gcS) = b*k*exp(gc) ----
    for (int i = tid; i < CH*HD; i += 512) {
        int t = i >> 7, k = i & 127;
        size_t go = tbase + (size_t)t*ROW + k;
        float bb = bS[t];
        float zb = bb * kS[t*P2S+k] * __expf(gcS[t*P2S+k]);
        qS [t*P2S+k] = bb * gv[go];
        gcS[t*P2S+k] = zb;
    }
    __syncthreads();

    // ---- blocked forward substitution (I+L) Z = RHS ----
#pragma unroll
    for (int ib = 0; ib < 4; ++ib) {
        int i0 = ib * 16;
        if (tid < 256) {
            float* Z = (tid < 128) ? (qS + tid) : (gcS + (tid - 128));
            for (int t = i0+1; t < i0+16; ++t) {
                float acc = 0.f;
                const float* lrow = Ls + (t*(t+1))/2;
                for (int s = i0; s < t; ++s) acc += lrow[s] * Z[s*P2S];
                Z[t*P2S] -= acc;
            }
        }
        __syncthreads();
        int rows = 48 - 16*ib;
        if (rows > 0) {
            int slots = rows * 128;
            for (int sl = tid; sl < slots; sl += 512) {
                int t  = i0 + 16 + (sl >> 7);
                int c2 = sl & 127;
                float* Z = (c2 < 64) ? (qS + c2*2) : (gcS + (c2-64)*2);
                float2 acc = make_float2(0.f, 0.f);
                const float* lrow = Ls + (t*(t+1))/2 + i0;
#pragma unroll
                for (int s = 0; s < 16; ++s) {
                    float lv = lrow[s];
                    float2 zv = *(const float2*)(Z + (i0+s)*P2S);
                    acc.x += lv*zv.x; acc.y += lv*zv.y;
                }
                float2 zt = *(float2*)(Z + t*P2S);
                zt.x -= acc.x; zt.y -= acc.y;
                *(float2*)(Z + t*P2S) = zt;
            }
        }
        __syncthreads();
    }

    // ---- write out: Vb -> gv, Kb -> gg ----
    for (int i = tid; i < CH*HD; i += 512) {
        int t = i >> 7, k = i & 127;
        size_t go = tbase + (size_t)t*ROW + k;
        gv[go] = qS [t*P2S+k];
        gg[go] = gcS[t*P2S+k];
    }
}

// =========================================================================
// Phase 3: sequential chunk scan, 1024 threads, 4-way split-K fused pass,
// 2-row-tile O-pass and S-update, register-prefetched staging.
// grid (8, NH) = 128 blocks.
// =========================================================================
#define ST3 132          // k-row stride (float4-aligned, even)
#define MT3 68           // M row stride

__global__ void __launch_bounds__(1024) k_phase3(float* __restrict__ out)
{
    extern __shared__ float sm[];
    float* KbS = sm;                 // 64*132
    float* QtS = KbS + CH*ST3;
    float* KrS = QtS + CH*ST3;
    float* MS  = KrS + CH*ST3;       // 64*68
    float* VbS = MS  + CH*MT3;       // 1024
    float* DS0 = VbS + 1024;         // 4 x 1024 D partials (DS0 = final)
    float* XS0 = DS0 + 4*1024;       // 4 x 1024 X partials (XS0 = final)
    float* cpS = XS0 + 4*1024;       // 128
    float* S   = cpS + HD;           // 128*16

    int h = blockIdx.y, j0 = blockIdx.x * 16, tid = threadIdx.x;
    int kq = tid >> 8;               // k-quarter 0..3
    int id = tid & 255;
    int t  = id >> 2, jq = id & 3;   // (t, j-quad) for fused pass
    int k0 = kq * 32;

    float4 rKb[2], rQt[2], rKr[2], rM, rVb;
    float rCp = 0.f;
    int stt[2], sk4[2];
#pragma unroll
    for (int i = 0; i < 2; ++i) {
        int idx = tid + i*1024;
        stt[i] = idx >> 5; sk4[i] = (idx & 31) * 4;
    }
    int mtt = tid >> 4, ms4 = (tid & 15) * 4;
    int vtt = tid >> 2, vj4 = (tid & 3) * 4;

    for (int i = tid; i < HD*16; i += 1024) S[i] = 0.f;

    // ---- prologue: stage chunk 0 directly ----
    {
        size_t tbase = ((size_t)h)*HD;
#pragma unroll
        for (int i = 0; i < 2; ++i) {
            size_t go = tbase + (size_t)stt[i]*ROW + sk4[i];
            *(float4*)(KbS + stt[i]*ST3 + sk4[i]) = *(const float4*)(gg + go);
            *(float4*)(QtS + stt[i]*ST3 + sk4[i]) = *(const float4*)(gq + go);
            *(float4*)(KrS + stt[i]*ST3 + sk4[i]) = *(const float4*)(gk + go);
        }
        *(float4*)(MS + mtt*MT3 + ms4) =
            *(const float4*)(gM + (size_t)h*CH*CH + mtt*64 + ms4);
        if (tid < 256)
            *(float4*)(VbS + vtt*16 + vj4) =
                *(const float4*)(gv + tbase + (size_t)vtt*ROW + j0 + vj4);
        if (tid < HD) cpS[tid] = gCp[h*HD + tid];
    }
    __syncthreads();

    for (int c = 0; c < NC; ++c) {
        // ---- prefetch chunk c+1 into registers ----
        if (c + 1 < NC) {
            size_t tbase1 = ((size_t)(c+1)*CH*NH + h)*HD;
#pragma unroll
            for (int i = 0; i < 2; ++i) {
                size_t go = tbase1 + (size_t)stt[i]*ROW + sk4[i];
                rKb[i] = *(const float4*)(gg + go);
                rQt[i] = *(const float4*)(gq + go);
                rKr[i] = *(const float4*)(gk + go);
            }
            rM = *(const float4*)(gM + (size_t)((c+1)*NH + h)*CH*CH + mtt*64 + ms4);
            if (tid < 256)
                rVb = *(const float4*)(gv + tbase1 + (size_t)vtt*ROW + j0 + vj4);
            if (tid < HD) rCp = gCp[((c+1)*NH+h)*HD + tid];
        }

        // ---- fused split-K: D-part = (kq0? Vb:0) - Kb@S_q, X-part = Qt@S_q --
        {
            float4 dA, xA;
            if (kq == 0) dA = *(const float4*)(VbS + id*4);
            else         dA = make_float4(0.f,0.f,0.f,0.f);
            xA = make_float4(0.f,0.f,0.f,0.f);
            const float* kbr = KbS + t*ST3 + k0;
            const float* qtr = QtS + t*ST3 + k0;
            const float* Sp  = S + k0*16 + jq*4;
#pragma unroll 4
            for (int k = 0; k < 32; ++k) {
                float kb = kbr[k], qv = qtr[k];
                float4 sv = *(const float4*)(Sp + k*16);
                dA.x -= kb*sv.x; dA.y -= kb*sv.y; dA.z -= kb*sv.z; dA.w -= kb*sv.w;
                xA.x += qv*sv.x; xA.y += qv*sv.y; xA.z += qv*sv.z; xA.w += qv*sv.w;
            }
            *(float4*)(DS0 + kq*1024 + id*4) = dA;
            *(float4*)(XS0 + kq*1024 + id*4) = xA;
        }
        __syncthreads();   // sync1: partials ready; KbS/QtS/VbS/S idle now

        // ---- commit group1 (c+1): KbS, QtS, VbS (all threads) ----
        if (c + 1 < NC) {
#pragma unroll
            for (int i = 0; i < 2; ++i) {
                *(float4*)(KbS + stt[i]*ST3 + sk4[i]) = rKb[i];
                *(float4*)(QtS + stt[i]*ST3 + sk4[i]) = rQt[i];
            }
            if (tid < 256) *(float4*)(VbS + vtt*16 + vj4) = rVb;
        }
        // ---- combine partials: 256 thr -> D, 256 thr -> X ----
        if (tid < 512) {
            float* A = (tid < 256) ? DS0 : XS0;
            int i4 = (tid & 255) * 4;
            float4 a = *(const float4*)(A + i4);
            float4 b = *(const float4*)(A + 1024 + i4);
            float4 d = *(const float4*)(A + 2048 + i4);
            float4 e = *(const float4*)(A + 3072 + i4);
            a.x += b.x + d.x + e.x; a.y += b.y + d.y + e.y;
            a.z += b.z + d.z + e.z; a.w += b.w + d.w + e.w;
            *(float4*)(A + i4) = a;
        }
        __syncthreads();   // sync2: D (DS0), X (XS0) final

        if (tid < 128) {
            // ---- O rows (t0, t0+1) = X + M@D (M upper-tri zero; shared D) ----
            int tp = tid >> 2, jqo = tid & 3;
            int t0 = tp * 2;
            float4 o0 = *(const float4*)(XS0 + (t0  )*16 + jqo*4);
            float4 o1 = *(const float4*)(XS0 + (t0+1)*16 + jqo*4);
            const float* mr0 = MS + t0*MT3;
            const float* mr1 = mr0 + MT3;
            int bound = ((t0+1) & ~7) + 8;
            for (int s = 0; s < bound; ++s) {
                float m0 = mr0[s], m1 = mr1[s];
                float4 dv = *(const float4*)(DS0 + s*16 + jqo*4);
                o0.x += m0*dv.x; o0.y += m0*dv.y; o0.z += m0*dv.z; o0.w += m0*dv.w;
                o1.x += m1*dv.x; o1.y += m1*dv.y; o1.z += m1*dv.z; o1.w += m1*dv.w;
            }
            *(float4*)(out + ((size_t)(c*CH + t0  )*NH + h)*HD + j0 + jqo*4) = o0;
            *(float4*)(out + ((size_t)(c*CH + t0+1)*NH + h)*HD + j0 + jqo*4) = o1;
        } else if (tid < 384) {
            // ---- S rows (krow0, krow0+1) = cp.*S + Kbar^T@D (float2 Kr) ----
            int u = tid - 128;
            int kp = u >> 2, jq2 = u & 3;
            int krow0 = kp * 2;
            float ca = cpS[krow0], cb2 = cpS[krow0+1];
            float4 sa = *(const float4*)(S + (krow0  )*16 + jq2*4);
            float4 sb = *(const float4*)(S + (krow0+1)*16 + jq2*4);
            sa.x *= ca;  sa.y *= ca;  sa.z *= ca;  sa.w *= ca;
            sb.x *= cb2; sb.y *= cb2; sb.z *= cb2; sb.w *= cb2;
            const float* kra = KrS + krow0;
#pragma unroll 4
            for (int s = 0; s < CH; ++s) {
                float2 kk = *(const float2*)(kra + s*ST3);   // even addr, 8B ok
                float4 dv = *(const float4*)(DS0 + s*16 + jq2*4);
                sa.x += kk.x*dv.x; sa.y += kk.x*dv.y; sa.z += kk.x*dv.z; sa.w += kk.x*dv.w;
                sb.x += kk.y*dv.x; sb.y += kk.y*dv.y; sb.z += kk.y*dv.z; sb.w += kk.y*dv.w;
            }
            *(float4*)(S + (krow0  )*16 + jq2*4) = sa;
            *(float4*)(S + (krow0+1)*16 + jq2*4) = sb;
        }
        __syncthreads();   // sync3: S updated; KrS/MS/cpS free

        // ---- commit group2 (c+1): KrS, MS, cpS ----
        if (c + 1 < NC) {
#pragma unroll
            for (int i = 0; i < 2; ++i)
                *(float4*)(KrS + stt[i]*ST3 + sk4[i]) = rKr[i];
            *(float4*)(MS + mtt*MT3 + ms4) = rM;
            if (tid < HD) cpS[tid] = rCp;
        }
        // no sync: group2 arrays are next read only after next sync2
        // (O-pass/S-update), with sync1+sync2 in between on every thread.
    }
}

// =========================================================================
extern "C" void kernel_launch(void* const* d_in, const int* in_sizes, int n_in,
                              void* d_out, int out_size)
{
    (void)in_sizes; (void)n_in; (void)out_size;
    const float* qkv  = (const float*)d_in[0];
    const float* fg   = (const float*)d_in[1];
    const float* beta = (const float*)d_in[2];
    const float* cw   = (const float*)d_in[3];
    const float* dtb  = (const float*)d_in[4];
    const float* alog = (const float*)d_in[5];
    float* out = (float*)d_out;

    int smem12 = (3*CH*P2S + 2080 + 64) * 4;                               // 109,952
    int smem3  = (3*CH*ST3 + CH*MT3 + 1024 + 8*1024 + HD + HD*16) * 4;     // 164,352
    cudaFuncSetAttribute(k_phase12, cudaFuncAttributeMaxDynamicSharedMemorySize, smem12);
    cudaFuncSetAttribute(k_phase3,  cudaFuncAttributeMaxDynamicSharedMemorySize, smem3);

    k_phase12<<<dim3(NC, NH), 512, smem12>>>(qkv, fg, beta, cw, dtb, alog);
    k_phase3<<<dim3(8, NH), 1024, smem3>>>(out);
}

// round 16
// speedup vs baseline: 1.5579x; 1.2562x over previous
#include <cuda_runtime.h>
#include <math.h>

#define T_TOK 8192
#define NH 16
#define HD 128
#define CH 64
#define NC 128
#define ROW (NH*HD)   // 2048

// ------------------- device scratch (allocation-free) -------------------
__device__ float gq [T_TOK*ROW];   // q~   (phase12 out)
__device__ float gk [T_TOK*ROW];   // Kbar
__device__ float gv [T_TOK*ROW];   // raw v (step A) -> Vb (phase12 out)
__device__ float gg [T_TOK*ROW];   // Kb
__device__ float gM [NC*NH*CH*CH];
__device__ float gCp[NC*NH*HD];

// =========================================================================
// Phase 1+2 fused (FROZEN from R15)
// =========================================================================
#define P2S 132   // padded row stride (float4-aligned)

__global__ void __launch_bounds__(512, 2) k_phase12(
    const float* __restrict__ qkv, const float* __restrict__ fg,
    const float* __restrict__ beta, const float* __restrict__ cw,
    const float* __restrict__ dtb, const float* __restrict__ alog)
{
    extern __shared__ float sm[];
    float* gcS = sm;               // 64*132 (gates -> cumsum -> ZB = Kb)
    float* qS  = gcS + CH*P2S;     // 64*132 (q -> ZA = Vb)
    float* kS  = qS  + CH*P2S;     // 64*132
    float* Ls  = kS  + CH*P2S;     // 2080 (triangular packed)
    float* bS  = Ls  + 2080;       // 64

    int c = blockIdx.x, h = blockIdx.y, tid = threadIdx.x;
    int w = tid >> 5, l = tid & 31;
    size_t tbase = ((size_t)c*CH*NH + h)*HD;

    int tloc0 = w * 4;
    int t0g = c * CH + tloc0;
    int d0 = l * 4;

    // ---- step A pass 1: q ----
    {
        int cx = h*HD + d0;
        float wx[4][4];
#pragma unroll
        for (int e = 0; e < 4; ++e)
#pragma unroll
            for (int j = 0; j < 4; ++j) wx[e][j] = cw[(cx+e)*4 + j];
        float px[3][4];
#pragma unroll
        for (int j = 0; j < 3; ++j) {
            int ts = t0g - 3 + j;
            if (ts >= 0) *(float4*)px[j] = *(const float4*)(qkv + (size_t)ts*(3*ROW) + cx);
            else { px[j][0]=px[j][1]=px[j][2]=px[j][3]=0.f; }
        }
#pragma unroll
        for (int tt = 0; tt < 4; ++tt) {
            int t = t0g + tt, tloc = tloc0 + tt;
            float rx[4];
            *(float4*)rx = *(const float4*)(qkv + (size_t)t*(3*ROW) + cx);
            float xx[4];
#pragma unroll
            for (int e = 0; e < 4; ++e) {
                float a = px[0][e]*wx[e][0] + px[1][e]*wx[e][1] + px[2][e]*wx[e][2] + rx[e]*wx[e][3];
                xx[e] = a / (1.f + __expf(-a));
            }
#pragma unroll
            for (int j = 0; j < 2; ++j)
#pragma unroll
                for (int e = 0; e < 4; ++e) px[j][e] = px[j+1][e];
#pragma unroll
            for (int e = 0; e < 4; ++e) px[2][e] = rx[e];
            float s2 = xx[0]*xx[0]+xx[1]*xx[1]+xx[2]*xx[2]+xx[3]*xx[3];
#pragma unroll
            for (int m = 16; m; m >>= 1) s2 += __shfl_xor_sync(~0u, s2, m);
            float rn = rsqrtf(s2 + 1e-6f) * 0.08838834764831845f;
            float ox[4];
#pragma unroll
            for (int e = 0; e < 4; ++e) ox[e] = xx[e] * rn;
            *(float4*)(qS + tloc*P2S + d0) = *(float4*)ox;
        }
    }
    // ---- step A pass 2: k ----
    {
        int cx = ROW + h*HD + d0;
        float wx[4][4];
#pragma unroll
        for (int e = 0; e < 4; ++e)
#pragma unroll
            for (int j = 0; j < 4; ++j) wx[e][j] = cw[(cx+e)*4 + j];
        float px[3][4];
#pragma unroll
        for (int j = 0; j < 3; ++j) {
            int ts = t0g - 3 + j;
            if (ts >= 0) *(float4*)px[j] = *(const float4*)(qkv + (size_t)ts*(3*ROW) + cx);
            else { px[j][0]=px[j][1]=px[j][2]=px[j][3]=0.f; }
        }
#pragma unroll
        for (int tt = 0; tt < 4; ++tt) {
            int t = t0g + tt, tloc = tloc0 + tt;
            float rx[4];
            *(float4*)rx = *(const float4*)(qkv + (size_t)t*(3*ROW) + cx);
            float xx[4];
#pragma unroll
            for (int e = 0; e < 4; ++e) {
                float a = px[0][e]*wx[e][0] + px[1][e]*wx[e][1] + px[2][e]*wx[e][2] + rx[e]*wx[e][3];
                xx[e] = a / (1.f + __expf(-a));
            }
#pragma unroll
            for (int j = 0; j < 2; ++j)
#pragma unroll
                for (int e = 0; e < 4; ++e) px[j][e] = px[j+1][e];
#pragma unroll
            for (int e = 0; e < 4; ++e) px[2][e] = rx[e];
            float s2 = xx[0]*xx[0]+xx[1]*xx[1]+xx[2]*xx[2]+xx[3]*xx[3];
#pragma unroll
            for (int m = 16; m; m >>= 1) s2 += __shfl_xor_sync(~0u, s2, m);
            float rn = rsqrtf(s2 + 1e-6f);
            float ox[4];
#pragma unroll
            for (int e = 0; e < 4; ++e) ox[e] = xx[e] * rn;
            *(float4*)(kS + tloc*P2S + d0) = *(float4*)ox;
        }
    }
    // ---- step A pass 3: v (global) + gates ----
    {
        int cx = 2*ROW + h*HD + d0;
        float wx[4][4];
#pragma unroll
        for (int e = 0; e < 4; ++e)
#pragma unroll
            for (int j = 0; j < 4; ++j) wx[e][j] = cw[(cx+e)*4 + j];
        float ea = expf(alog[h]);
        float dtv[4];
        *(float4*)dtv = *(const float4*)(dtb + h*HD + d0);
        float px[3][4];
#pragma unroll
        for (int j = 0; j < 3; ++j) {
            int ts = t0g - 3 + j;
            if (ts >= 0) *(float4*)px[j] = *(const float4*)(qkv + (size_t)ts*(3*ROW) + cx);
            else { px[j][0]=px[j][1]=px[j][2]=px[j][3]=0.f; }
        }
#pragma unroll
        for (int tt = 0; tt < 4; ++tt) {
            int t = t0g + tt, tloc = tloc0 + tt;
            float rx[4], fgv[4];
            *(float4*)rx = *(const float4*)(qkv + (size_t)t*(3*ROW) + cx);
            *(float4*)fgv = *(const float4*)(fg + (size_t)t*ROW + h*HD + d0);
            float xx[4], og[4];
#pragma unroll
            for (int e = 0; e < 4; ++e) {
                float a = px[0][e]*wx[e][0] + px[1][e]*wx[e][1] + px[2][e]*wx[e][2] + rx[e]*wx[e][3];
                xx[e] = a / (1.f + __expf(-a));
                float gr = fgv[e] + dtv[e];
                float sp = (gr > 20.f) ? gr : log1pf(__expf(gr));
                og[e] = -ea * sp;
            }
#pragma unroll
            for (int j = 0; j < 2; ++j)
#pragma unroll
                for (int e = 0; e < 4; ++e) px[j][e] = px[j+1][e];
#pragma unroll
            for (int e = 0; e < 4; ++e) px[2][e] = rx[e];
            *(float4*)(gv + tbase + (size_t)tloc*ROW + d0) = *(float4*)xx;
            *(float4*)(gcS + tloc*P2S + d0) = *(float4*)og;
            if (l == 0) {
                float bb = beta[t*NH + h];
                bS[tloc] = 1.f / (1.f + __expf(-bb));
            }
        }
    }
    __syncthreads();

    if (tid < HD) {
        float run = 0.f;
        for (int t = 0; t < CH; ++t) { run += gcS[t*P2S+tid]; gcS[t*P2S+tid] = run; }
    }
    __syncthreads();

    for (int i = tid; i < CH*HD; i += 512) {
        int t = i >> 7, k = i & 127;
        float gct = gcS[t*P2S+k];
        float g63 = gcS[63*P2S+k];
        size_t go = tbase + (size_t)t*ROW + k;
        gq[go] = qS[t*P2S+k] * __expf(gct);
        gk[go] = kS[t*P2S+k] * __expf(g63 - gct);
    }
    if (tid < HD) gCp[(c*NH+h)*HD + tid] = __expf(gcS[63*P2S+tid]);

    size_t mbase = (size_t)(c*NH + h) * CH * CH;
    {
        int l5 = tid & 31, tr = l5 >> 2, sc = l5 & 3;
        for (int tile = w; tile < 72; tile += 16) {
            int i = 0;
            while ((i+1)*(i+2) <= tile) ++i;
            int j = tile - i*(i+1);
            int t = i*8 + tr, s = j*4 + sc;
            const float* gtr = gcS + t*P2S; const float* gsr = gcS + s*P2S;
            const float* ktr = kS  + t*P2S; const float* ksr = kS  + s*P2S;
            const float* qtr = qS  + t*P2S;
            float a = 0.f, m = 0.f;
#pragma unroll 4
            for (int k = 0; k < HD; k += 4) {
                float4 g1 = *(const float4*)(gtr + k);
                float4 g0 = *(const float4*)(gsr + k);
                float4 kt4 = *(const float4*)(ktr + k);
                float4 ks4 = *(const float4*)(ksr + k);
                float4 qt4 = *(const float4*)(qtr + k);
                float e, kv;
                e = __expf(g1.x - g0.x); kv = ks4.x * e; a += kt4.x*kv; m += qt4.x*kv;
                e = __expf(g1.y - g0.y); kv = ks4.y * e; a += kt4.y*kv; m += qt4.y*kv;
                e = __expf(g1.z - g0.z); kv = ks4.z * e; a += kt4.z*kv; m += qt4.z*kv;
                e = __expf(g1.w - g0.w); kv = ks4.w * e; a += kt4.w*kv; m += qt4.w*kv;
            }
            if (s <= t) gM[mbase + t*64 + s] = m;
            if (s <  t) Ls[(t*(t+1))/2 + s] = bS[t] * a;
        }
    }
    // zero upper triangle of M (phase3's O-GEMM relies on M[t][s>t] == 0)
    for (int i = tid; i < 4096; i += 512) {
        int t = i >> 6, s = i & 63;
        if (s > t) gM[mbase + i] = 0.f;
    }
    __syncthreads();

    for (int i = tid; i < CH*HD; i += 512) {
        int t = i >> 7, k = i & 127;
        size_t go = tbase + (size_t)t*ROW + k;
        float bb = bS[t];
        float zb = bb * kS[t*P2S+k] * __expf(gcS[t*P2S+k]);
        qS [t*P2S+k] = bb * gv[go];
        gcS[t*P2S+k] = zb;
    }
    __syncthreads();

#pragma unroll
    for (int ib = 0; ib < 4; ++ib) {
        int i0 = ib * 16;
        if (tid < 256) {
            float* Z = (tid < 128) ? (qS + tid) : (gcS + (tid - 128));
            for (int t = i0+1; t < i0+16; ++t) {
                float acc = 0.f;
                const float* lrow = Ls + (t*(t+1))/2;
                for (int s = i0; s < t; ++s) acc += lrow[s] * Z[s*P2S];
                Z[t*P2S] -= acc;
            }
        }
        __syncthreads();
        int rows = 48 - 16*ib;
        if (rows > 0) {
            int slots = rows * 128;
            for (int sl = tid; sl < slots; sl += 512) {
                int t  = i0 + 16 + (sl >> 7);
                int c2 = sl & 127;
                float* Z = (c2 < 64) ? (qS + c2*2) : (gcS + (c2-64)*2);
                float2 acc = make_float2(0.f, 0.f);
                const float* lrow = Ls + (t*(t+1))/2 + i0;
#pragma unroll
                for (int s = 0; s < 16; ++s) {
                    float lv = lrow[s];
                    float2 zv = *(const float2*)(Z + (i0+s)*P2S);
                    acc.x += lv*zv.x; acc.y += lv*zv.y;
                }
                float2 zt = *(float2*)(Z + t*P2S);
                zt.x -= acc.x; zt.y -= acc.y;
                *(float2*)(Z + t*P2S) = zt;
            }
        }
        __syncthreads();
    }

    for (int i = tid; i < CH*HD; i += 512) {
        int t = i >> 7, k = i & 127;
        size_t go = tbase + (size_t)t*ROW + k;
        gv[go] = qS [t*P2S+k];
        gg[go] = gcS[t*P2S+k];
    }
}

// =========================================================================
// Phase 3: tensor-core (mma.sync m16n8k8 tf32, 3xTF32 split) chunk scan.
// grid (8, NH) = 128 blocks, 1024 threads.
// =========================================================================
#define ST3 132
#define MT3 68

__device__ __forceinline__ void mma8(float4& c, unsigned a0, unsigned a1,
                                     unsigned a2, unsigned a3,
                                     unsigned b0, unsigned b1)
{
    asm volatile(
        "mma.sync.aligned.m16n8k8.row.col.f32.tf32.tf32.f32 "
        "{%0,%1,%2,%3}, {%4,%5,%6,%7}, {%8,%9}, {%0,%1,%2,%3};"
        : "+f"(c.x), "+f"(c.y), "+f"(c.z), "+f"(c.w)
        : "r"(a0), "r"(a1), "r"(a2), "r"(a3), "r"(b0), "r"(b1));
}

__device__ __forceinline__ void split_tf32(float x, unsigned& hi, unsigned& lo)
{
    unsigned xu = __float_as_uint(x);
    hi = xu & 0xffffe000u;
    lo = __float_as_uint(x - __uint_as_float(hi));
}

// C += A*B with ~fp32 precision: hi*hi + hi*lo + lo*hi
__device__ __forceinline__ void mma3(float4& C, float A0, float A1, float A2,
                                     float A3, float B0, float B1)
{
    unsigned ah0,al0,ah1,al1,ah2,al2,ah3,al3,bh0,bl0,bh1,bl1;
    split_tf32(A0,ah0,al0); split_tf32(A1,ah1,al1);
    split_tf32(A2,ah2,al2); split_tf32(A3,ah3,al3);
    split_tf32(B0,bh0,bl0); split_tf32(B1,bh1,bl1);
    mma8(C, ah0,ah1,ah2,ah3, bh0,bh1);
    mma8(C, ah0,ah1,ah2,ah3, bl0,bl1);
    mma8(C, al0,al1,al2,al3, bh0,bh1);
}

__device__ __forceinline__ void cpa16(float* smem_dst, const float* gsrc)
{
    unsigned s = (unsigned)__cvta_generic_to_shared(smem_dst);
    asm volatile("cp.async.ca.shared.global [%0], [%1], 16;" :: "r"(s), "l"(gsrc));
}
#define CP_COMMIT() asm volatile("cp.async.commit_group;" ::: "memory")
#define CP_WAIT0()  asm volatile("cp.async.wait_group 0;" ::: "memory")

__global__ void __launch_bounds__(1024) k_phase3(float* __restrict__ out)
{
    extern __shared__ float sm[];
    float* KbS = sm;                 // 64*132
    float* QtS = KbS + CH*ST3;       // 64*132
    float* KrS = QtS + CH*ST3;       // 64*132
    float* MS  = KrS + CH*ST3;       // 64*68
    float* VbA = MS  + CH*MT3;       // 1024
    float* VbB = VbA + 1024;         // 1024
    float* DS  = VbB + 1024;         // 1024
    float* XS  = DS  + 1024;         // 1024
    float* PS0 = XS  + 1024;         // 2048 (fused partial ks=0; S-GEMM result)
    float* PS1 = PS0 + 2048;         // 2048 (fused partial ks=1; O partials)
    float* cpA = PS1 + 2048;         // 128
    float* cpB = cpA + 128;          // 128
    float* S   = cpB + 128;          // 128*16

    float* PO0 = PS1;                // 64*16 O partial ks=0 (alias)
    float* PO1 = PS1 + 1024;         // 64*16 O partial ks=1 (alias)

    int h = blockIdx.y, j0 = blockIdx.x * 16, tid = threadIdx.x;
    int wid = tid >> 5, lane = tid & 31;
    int g = lane >> 2, tg = lane & 3;

    // ---- prologue: stage chunk 0 + zero S ----
    {
        size_t tb = ((size_t)h)*HD;
#pragma unroll
        for (int i = 0; i < 2; ++i) {
            int idx = tid + i*1024;
            int row = idx >> 5, c4 = (idx & 31) * 4;
            size_t go = tb + (size_t)row*ROW + c4;
            *(float4*)(KbS + row*ST3 + c4) = *(const float4*)(gg + go);
            *(float4*)(QtS + row*ST3 + c4) = *(const float4*)(gq + go);
            *(float4*)(KrS + row*ST3 + c4) = *(const float4*)(gk + go);
        }
        {
            int row = tid >> 4, c4m = (tid & 15) * 4;
            *(float4*)(MS + row*MT3 + c4m) =
                *(const float4*)(gM + (size_t)h*CH*CH + row*64 + c4m);
        }
        if (tid < 256) {
            int tt = tid >> 2, c4 = (tid & 3) * 4;
            *(float4*)(VbA + tt*16 + c4) =
                *(const float4*)(gv + tb + (size_t)tt*ROW + j0 + c4);
        }
        if (tid < HD) cpA[tid] = gCp[h*HD + tid];
        for (int i = tid; i < HD*16; i += 1024) S[i] = 0.f;
    }
    __syncthreads();

    for (int c = 0; c < NC; ++c) {
        float* VbC = (c & 1) ? VbB : VbA;
        float* VbN = (c & 1) ? VbA : VbB;
        float* cpC = (c & 1) ? cpB : cpA;
        float* cpN = (c & 1) ? cpA : cpB;

        // ================== fused GEMM: [P;X] = [Kb;Qt] @ S ==================
        {
            int mt = wid & 7, nt = (wid >> 3) & 1, ks = wid >> 4;
            const float* Arow = (mt < 4) ? (KbS + (mt*16)*ST3)
                                         : (QtS + ((mt-4)*16)*ST3);
            const float* A0p = Arow + g*ST3;
            const float* A1p = Arow + (g+8)*ST3;
            int bcol = nt*8 + g;
            float4 Cacc = make_float4(0.f,0.f,0.f,0.f);
            int kk = ks*64;
#pragma unroll
            for (int kstep = 0; kstep < 8; ++kstep, kk += 8) {
                float a0 = A0p[kk+tg],   a1 = A1p[kk+tg];
                float a2 = A0p[kk+tg+4], a3 = A1p[kk+tg+4];
                float b0 = S[(kk+tg)*16 + bcol];
                float b1 = S[(kk+tg+4)*16 + bcol];
                mma3(Cacc, a0,a1,a2,a3, b0,b1);
            }
            float* PSx = ks ? PS1 : PS0;
            int prow = (mt*16 + g)*16 + nt*8 + 2*tg;
            *(float2*)(PSx + prow)        = make_float2(Cacc.x, Cacc.y);
            *(float2*)(PSx + prow + 128)  = make_float2(Cacc.z, Cacc.w);  // row+8
        }
        __syncthreads();   // sync1

        // ---- issue g1 cp.async (Kb, Qt for c+1) ----
        if (c + 1 < NC) {
            size_t tb1 = ((size_t)(c+1)*CH*NH + h)*HD;
#pragma unroll
            for (int i = 0; i < 2; ++i) {
                int idx = tid + i*1024;
                int row = idx >> 5, c4 = (idx & 31) * 4;
                size_t go = tb1 + (size_t)row*ROW + c4;
                cpa16(KbS + row*ST3 + c4, gg + go);
                cpa16(QtS + row*ST3 + c4, gq + go);
            }
        }
        CP_COMMIT();

        // ---- combine: D = Vb - (P0+P1), X = (P0+P1) ----
        if (tid < 512) {
            int r = tid >> 2, c4 = (tid & 3) * 4;
            float4 p0 = *(const float4*)(PS0 + r*16 + c4);
            float4 p1 = *(const float4*)(PS1 + r*16 + c4);
            p0.x += p1.x; p0.y += p1.y; p0.z += p1.z; p0.w += p1.w;
            if (r < 64) {
                float4 vb = *(const float4*)(VbC + r*16 + c4);
                vb.x -= p0.x; vb.y -= p0.y; vb.z -= p0.z; vb.w -= p0.w;
                *(float4*)(DS + r*16 + c4) = vb;
            } else {
                *(float4*)(XS + (r-64)*16 + c4) = p0;
            }
        }
        __syncthreads();   // sync2

        // ============ S-GEMM (warps 0-15) and O-GEMM (warps 16-31) ==========
        if (wid < 16) {
            // P2(128x16) = Kbar^T(128x64) @ D(64x16)
            int mt = wid & 7, nt = wid >> 3;
            int arow = mt*16 + g;
            int bcol = nt*8 + g;
            float4 Cacc = make_float4(0.f,0.f,0.f,0.f);
#pragma unroll
            for (int kstep = 0; kstep < 8; ++kstep) {
                int kk = kstep*8;
                float a0 = KrS[(kk+tg)*ST3 + arow];
                float a1 = KrS[(kk+tg)*ST3 + arow + 8];
                float a2 = KrS[(kk+tg+4)*ST3 + arow];
                float a3 = KrS[(kk+tg+4)*ST3 + arow + 8];
                float b0 = DS[(kk+tg)*16 + bcol];
                float b1 = DS[(kk+tg+4)*16 + bcol];
                mma3(Cacc, a0,a1,a2,a3, b0,b1);
            }
            int prow = (mt*16 + g)*16 + nt*8 + 2*tg;
            *(float2*)(PS0 + prow)       = make_float2(Cacc.x, Cacc.y);
            *(float2*)(PS0 + prow + 128) = make_float2(Cacc.z, Cacc.w);
        } else {
            // PO(64x16) = M(64x64) @ D(64x16), 2-way split-K
            int u = wid - 16;
            int mt = u & 3, nt = (u >> 2) & 1, ks = u >> 3;
            const float* A0p = MS + (mt*16 + g)*MT3;
            const float* A1p = A0p + 8*MT3;
            int bcol = nt*8 + g;
            float4 Cacc = make_float4(0.f,0.f,0.f,0.f);
            int kk = ks*32;
#pragma unroll
            for (int kstep = 0; kstep < 4; ++kstep, kk += 8) {
                float a0 = A0p[kk+tg],   a1 = A1p[kk+tg];
                float a2 = A0p[kk+tg+4], a3 = A1p[kk+tg+4];
                float b0 = DS[(kk+tg)*16 + bcol];
                float b1 = DS[(kk+tg+4)*16 + bcol];
                mma3(Cacc, a0,a1,a2,a3, b0,b1);
            }
            float* POx = ks ? PO1 : PO0;
            int prow = (mt*16 + g)*16 + nt*8 + 2*tg;
            *(float2*)(POx + prow)       = make_float2(Cacc.x, Cacc.y);
            *(float2*)(POx + prow + 128) = make_float2(Cacc.z, Cacc.w);
        }
        __syncthreads();   // sync3

        // ---- issue g2 cp.async (Kr, M, Vb[nxt], cp[nxt]) ----
        if (c + 1 < NC) {
            size_t tb1 = ((size_t)(c+1)*CH*NH + h)*HD;
#pragma unroll
            for (int i = 0; i < 2; ++i) {
                int idx = tid + i*1024;
                int row = idx >> 5, c4 = (idx & 31) * 4;
                cpa16(KrS + row*ST3 + c4, gk + tb1 + (size_t)row*ROW + c4);
            }
            {
                int row = tid >> 4, c4m = (tid & 15) * 4;
                cpa16(MS + row*MT3 + c4m,
                      gM + (size_t)((c+1)*NH + h)*CH*CH + row*64 + c4m);
            }
            if (tid < 256) {
                int tt = tid >> 2, c4 = (tid & 3) * 4;
                cpa16(VbN + tt*16 + c4, gv + tb1 + (size_t)tt*ROW + j0 + c4);
            }
            if (tid < 32)
                cpa16(cpN + tid*4, gCp + ((size_t)(c+1)*NH + h)*HD + tid*4);
        }
        CP_COMMIT();

        // ---- epilogue: O out (256 thr) || S update (512 thr) ----
        if (tid < 256) {
            int r = tid >> 2, c4 = (tid & 3) * 4;
            float4 o  = *(const float4*)(XS  + r*16 + c4);
            float4 q0 = *(const float4*)(PO0 + r*16 + c4);
            float4 q1 = *(const float4*)(PO1 + r*16 + c4);
            o.x += q0.x + q1.x; o.y += q0.y + q1.y;
            o.z += q0.z + q1.z; o.w += q0.w + q1.w;
            *(float4*)(out + ((size_t)(c*CH + r)*NH + h)*HD + j0 + c4) = o;
        } else if (tid < 768) {
            int u2 = tid - 256;
            int r = u2 >> 2, c4 = (u2 & 3) * 4;
            float cp = cpC[r];
            float4 sv = *(const float4*)(S + r*16 + c4);
            float4 ps = *(const float4*)(PS0 + r*16 + c4);
            sv.x = cp*sv.x + ps.x; sv.y = cp*sv.y + ps.y;
            sv.z = cp*sv.z + ps.z; sv.w = cp*sv.w + ps.w;
            *(float4*)(S + r*16 + c4) = sv;
        }

        CP_WAIT0();
        __syncthreads();   // sync4
    }
}

// =========================================================================
extern "C" void kernel_launch(void* const* d_in, const int* in_sizes, int n_in,
                              void* d_out, int out_size)
{
    (void)in_sizes; (void)n_in; (void)out_size;
    const float* qkv  = (const float*)d_in[0];
    const float* fg   = (const float*)d_in[1];
    const float* beta = (const float*)d_in[2];
    const float* cw   = (const float*)d_in[3];
    const float* dtb  = (const float*)d_in[4];
    const float* alog = (const float*)d_in[5];
    float* out = (float*)d_out;

    int smem12 = (3*CH*P2S + 2080 + 64) * 4;                         // 109,952
    int smem3  = (3*CH*ST3 + CH*MT3 + 2*1024 + 2*1024 + 2*2048
                  + 2*128 + HD*16) * 4;                               // 160,768
    cudaFuncSetAttribute(k_phase12, cudaFuncAttributeMaxDynamicSharedMemorySize, smem12);
    cudaFuncSetAttribute(k_phase3,  cudaFuncAttributeMaxDynamicSharedMemorySize, smem3);

    k_phase12<<<dim3(NC, NH), 512, smem12>>>(qkv, fg, beta, cw, dtb, alog);
    k_phase3<<<dim3(8, NH), 1024, smem3>>>(out);
}